// round 1
// baseline (speedup 1.0000x reference)
#include <cuda_runtime.h>
#include <math.h>

#define BATCH 4
#define S_LEN 2048
#define HID   1024
#define NH    16
#define HD    64

// Scratch (device globals: allocation-free per harness rules)
__device__ float g_qkv[(size_t)BATCH * S_LEN * 3 * HID];   // [B, S, 3*HID], head h: q@h*192, k@h*192+64, v@h*192+128
__device__ float g_ctx[(size_t)BATCH * S_LEN * HID];       // [B, S, HID]

// ---------------------------------------------------------------------------
// SGEMM:  C[M,N] = A[M,K] @ B[K,N] + bias[N]
// 128x128 block tile, BK=16, 256 threads, 8x8 per-thread microtile.
// ---------------------------------------------------------------------------
__global__ __launch_bounds__(256) void sgemm_bias_kernel(
    const float* __restrict__ A, const float* __restrict__ B,
    const float* __restrict__ bias, float* __restrict__ C,
    int M, int N, int K)
{
    const int BK = 16;
    __shared__ float As[BK][128];   // transposed A tile: As[k][m]
    __shared__ float Bs[BK][128];   // Bs[k][n]

    int tid = threadIdx.x;
    int tx = tid & 15;              // col group
    int ty = tid >> 4;              // row group
    int row0 = blockIdx.y * 128;
    int col0 = blockIdx.x * 128;

    // load mappings
    int ar = tid >> 2;              // 0..63
    int ak = (tid & 3) << 2;        // 0,4,8,12
    int bk = tid >> 5;              // 0..7
    int bn = (tid & 31) << 2;       // 0..124

    float acc[8][8];
#pragma unroll
    for (int i = 0; i < 8; i++)
#pragma unroll
        for (int j = 0; j < 8; j++) acc[i][j] = 0.f;

    for (int k0 = 0; k0 < K; k0 += BK) {
        float4 a0 = *(const float4*)(A + (size_t)(row0 + ar)      * K + k0 + ak);
        float4 a1 = *(const float4*)(A + (size_t)(row0 + ar + 64) * K + k0 + ak);
        float4 b0 = *(const float4*)(B + (size_t)(k0 + bk)     * N + col0 + bn);
        float4 b1 = *(const float4*)(B + (size_t)(k0 + bk + 8) * N + col0 + bn);

        As[ak + 0][ar] = a0.x; As[ak + 1][ar] = a0.y;
        As[ak + 2][ar] = a0.z; As[ak + 3][ar] = a0.w;
        As[ak + 0][ar + 64] = a1.x; As[ak + 1][ar + 64] = a1.y;
        As[ak + 2][ar + 64] = a1.z; As[ak + 3][ar + 64] = a1.w;
        *(float4*)&Bs[bk][bn]     = b0;
        *(float4*)&Bs[bk + 8][bn] = b1;
        __syncthreads();

#pragma unroll
        for (int kk = 0; kk < BK; kk++) {
            float4 a04 = *(float4*)&As[kk][ty * 8];
            float4 a14 = *(float4*)&As[kk][ty * 8 + 4];
            float4 b04 = *(float4*)&Bs[kk][tx * 8];
            float4 b14 = *(float4*)&Bs[kk][tx * 8 + 4];
            float a[8] = {a04.x, a04.y, a04.z, a04.w, a14.x, a14.y, a14.z, a14.w};
            float b[8] = {b04.x, b04.y, b04.z, b04.w, b14.x, b14.y, b14.z, b14.w};
#pragma unroll
            for (int i = 0; i < 8; i++)
#pragma unroll
                for (int j = 0; j < 8; j++)
                    acc[i][j] += a[i] * b[j];
        }
        __syncthreads();
    }

#pragma unroll
    for (int i = 0; i < 8; i++) {
        int r = row0 + ty * 8 + i;
#pragma unroll
        for (int j = 0; j < 8; j += 4) {
            int c = col0 + tx * 8 + j;
            float4 o;
            o.x = acc[i][j + 0] + bias[c + 0];
            o.y = acc[i][j + 1] + bias[c + 1];
            o.z = acc[i][j + 2] + bias[c + 2];
            o.w = acc[i][j + 3] + bias[c + 3];
            *(float4*)(C + (size_t)r * N + c) = o;
        }
    }
}

// ---------------------------------------------------------------------------
// Flash attention (fp32, causal). One CTA = 64 q-rows of one (b, h).
// smem: Q[64][AS], KV[64][AS] (K then reused for V), S[64][AS], rowC/rowL.
// 256 threads. GEMM threads: (tr=tid/16 -> 4 rows, tc=tid%16).
//   GEMM1 cols: tc + 16*j (bank-friendly K reads over contiguous kk)
//   GEMM2 cols: tc*4 + j (contiguous d -> float4 V reads, float4 gmem stores)
// Softmax threads: row = tid/4, 4 threads per row, shfl reduction.
// ---------------------------------------------------------------------------
#define AS 68

__global__ __launch_bounds__(256) void attn_kernel(
    const float* __restrict__ qkv, float* __restrict__ ctx)
{
    extern __shared__ float sm[];
    float* Qs   = sm;                 // 64*AS
    float* KVs  = sm + 64 * AS;       // 64*AS
    float* Ss   = sm + 2 * 64 * AS;   // 64*AS
    float* rowC = sm + 3 * 64 * AS;   // 64
    float* rowL = rowC + 64;          // 64

    int tid = threadIdx.x;
    int qt = blockIdx.x;              // q tile 0..31
    int h  = blockIdx.y;
    int b  = blockIdx.z;
    int q0 = qt * 64;
    const float* base = qkv + (size_t)b * S_LEN * (3 * HID) + h * (3 * HD);

    int lr = tid >> 4;                // 0..15
    int ld = (tid & 15) << 2;         // 0..60 step 4

    // Load Q tile once
#pragma unroll
    for (int rr = lr; rr < 64; rr += 16)
        *(float4*)&Qs[rr * AS + ld] =
            *(const float4*)&base[(size_t)(q0 + rr) * (3 * HID) + ld];

    int tr = tid >> 4, tc = tid & 15;
    int srow = tid >> 2, sseg = tid & 3;

    float m_i = -INFINITY, l_i = 0.f;
    float acc[4][4];
#pragma unroll
    for (int i = 0; i < 4; i++)
#pragma unroll
        for (int j = 0; j < 4; j++) acc[i][j] = 0.f;

    for (int jt = 0; jt <= qt; jt++) {
        int k0 = jt * 64;
        __syncthreads();   // protect KVs/Ss from previous iteration's readers

        // Load K tile
#pragma unroll
        for (int rr = lr; rr < 64; rr += 16)
            *(float4*)&KVs[rr * AS + ld] =
                *(const float4*)&base[(size_t)(k0 + rr) * (3 * HID) + HD + ld];
        __syncthreads();

        // GEMM1: S = scale * Q @ K^T, causal mask
        float s[4][4];
#pragma unroll
        for (int i = 0; i < 4; i++)
#pragma unroll
            for (int j = 0; j < 4; j++) s[i][j] = 0.f;

#pragma unroll
        for (int kk = 0; kk < 64; kk += 4) {
            float qv[4][4], kv[4][4];
#pragma unroll
            for (int i = 0; i < 4; i++) {
                float4 q4 = *(float4*)&Qs[(tr * 4 + i) * AS + kk];
                qv[i][0] = q4.x; qv[i][1] = q4.y; qv[i][2] = q4.z; qv[i][3] = q4.w;
            }
#pragma unroll
            for (int j = 0; j < 4; j++) {
                float4 k4 = *(float4*)&KVs[(tc + 16 * j) * AS + kk];
                kv[j][0] = k4.x; kv[j][1] = k4.y; kv[j][2] = k4.z; kv[j][3] = k4.w;
            }
#pragma unroll
            for (int i = 0; i < 4; i++)
#pragma unroll
                for (int j = 0; j < 4; j++)
#pragma unroll
                    for (int kc = 0; kc < 4; kc++)
                        s[i][j] += qv[i][kc] * kv[j][kc];
        }
#pragma unroll
        for (int i = 0; i < 4; i++)
#pragma unroll
            for (int j = 0; j < 4; j++) {
                int qg = q0 + tr * 4 + i;
                int kg = k0 + tc + 16 * j;
                float v = s[i][j] * 0.125f;
                if (kg > qg) v = -1e30f;
                Ss[(tr * 4 + i) * AS + tc + 16 * j] = v;
            }
        __syncthreads();

        // Load V tile (overwrites K — K no longer needed) ...
#pragma unroll
        for (int rr = lr; rr < 64; rr += 16)
            *(float4*)&KVs[rr * AS + ld] =
                *(const float4*)&base[(size_t)(k0 + rr) * (3 * HID) + 2 * HD + ld];

        // ... while doing online softmax on Ss
        {
            float* sp = &Ss[srow * AS + sseg * 16];
            float tm = -INFINITY;
#pragma unroll
            for (int c = 0; c < 16; c++) tm = fmaxf(tm, sp[c]);
            tm = fmaxf(tm, __shfl_xor_sync(0xffffffffu, tm, 1));
            tm = fmaxf(tm, __shfl_xor_sync(0xffffffffu, tm, 2));
            float m_new = fmaxf(m_i, tm);
            float csum = 0.f;
#pragma unroll
            for (int c = 0; c < 16; c++) {
                float p = __expf(sp[c] - m_new);
                sp[c] = p;
                csum += p;
            }
            csum += __shfl_xor_sync(0xffffffffu, csum, 1);
            csum += __shfl_xor_sync(0xffffffffu, csum, 2);
            float corr = __expf(m_i - m_new);
            l_i = l_i * corr + csum;
            m_i = m_new;
            if (sseg == 0) {
                rowC[srow] = corr;
                if (jt == qt) rowL[srow] = l_i;
            }
        }
        __syncthreads();

        // GEMM2: acc = acc*corr + P @ V
        float cf[4];
#pragma unroll
        for (int i = 0; i < 4; i++) cf[i] = rowC[tr * 4 + i];
#pragma unroll
        for (int i = 0; i < 4; i++)
#pragma unroll
            for (int j = 0; j < 4; j++) acc[i][j] *= cf[i];

#pragma unroll
        for (int cc = 0; cc < 64; cc += 4) {
            float pv[4][4], vv[4][4];
#pragma unroll
            for (int i = 0; i < 4; i++) {
                float4 p4 = *(float4*)&Ss[(tr * 4 + i) * AS + cc];
                pv[i][0] = p4.x; pv[i][1] = p4.y; pv[i][2] = p4.z; pv[i][3] = p4.w;
            }
#pragma unroll
            for (int c = 0; c < 4; c++) {
                float4 v4 = *(float4*)&KVs[(cc + c) * AS + tc * 4];
                vv[c][0] = v4.x; vv[c][1] = v4.y; vv[c][2] = v4.z; vv[c][3] = v4.w;
            }
#pragma unroll
            for (int i = 0; i < 4; i++)
#pragma unroll
                for (int j = 0; j < 4; j++)
#pragma unroll
                    for (int c = 0; c < 4; c++)
                        acc[i][j] += pv[i][c] * vv[c][j];
        }
    }

    // Epilogue: normalize and write context (d = tc*4 + j, contiguous)
#pragma unroll
    for (int i = 0; i < 4; i++) {
        float inv = 1.0f / rowL[tr * 4 + i];
        float4 o;
        o.x = acc[i][0] * inv;
        o.y = acc[i][1] * inv;
        o.z = acc[i][2] * inv;
        o.w = acc[i][3] * inv;
        *(float4*)&ctx[((size_t)b * S_LEN + q0 + tr * 4 + i) * HID + h * HD + tc * 4] = o;
    }
}

// ---------------------------------------------------------------------------
// kernel_launch
// Inputs (metadata order): x, mask(bool, ignored: causal known), w_qkv, b_qkv,
//                          w_out, b_out. Output: [B, S, HID] float32.
// ---------------------------------------------------------------------------
extern "C" void kernel_launch(void* const* d_in, const int* in_sizes, int n_in,
                              void* d_out, int out_size)
{
    const float* x     = (const float*)d_in[0];
    const float* w_qkv = (const float*)d_in[2];
    const float* b_qkv = (const float*)d_in[3];
    const float* w_out = (const float*)d_in[4];
    const float* b_out = (const float*)d_in[5];
    float* out = (float*)d_out;

    float* qkv_ptr = nullptr;
    float* ctx_ptr = nullptr;
    cudaGetSymbolAddress((void**)&qkv_ptr, g_qkv);
    cudaGetSymbolAddress((void**)&ctx_ptr, g_ctx);

    const int M = BATCH * S_LEN;   // 8192

    // 1) QKV projection: [8192,1024] @ [1024,3072] + b
    {
        dim3 grid((3 * HID) / 128, M / 128);
        sgemm_bias_kernel<<<grid, 256>>>(x, w_qkv, b_qkv, qkv_ptr, M, 3 * HID, HID);
    }

    // 2) Causal flash attention
    {
        int smem = (3 * 64 * AS + 128) * (int)sizeof(float);   // 52736 B
        cudaFuncSetAttribute(attn_kernel,
                             cudaFuncAttributeMaxDynamicSharedMemorySize, smem);
        dim3 grid(S_LEN / 64, NH, BATCH);
        attn_kernel<<<grid, 256, smem>>>(qkv_ptr, ctx_ptr);
    }

    // 3) Output projection: [8192,1024] @ [1024,1024] + b
    {
        dim3 grid(HID / 128, M / 128);
        sgemm_bias_kernel<<<grid, 256>>>(ctx_ptr, w_out, b_out, out, M, HID, HID);
    }
}

// round 3
// speedup vs baseline: 1.5509x; 1.5509x over previous
#include <cuda_runtime.h>
#include <cuda_bf16.h>
#include <math.h>
#include <stdint.h>

#define BATCH 4
#define S_LEN 2048
#define HID   1024
#define NH    16
#define HD    64

// ---------------------------------------------------------------------------
// Scratch (device globals: allocation-free per harness rules)
// ---------------------------------------------------------------------------
__device__ float g_qkv[(size_t)BATCH * S_LEN * 3 * HID];       // [B,S,3*HID]
__device__ float g_ctx[(size_t)BATCH * S_LEN * HID];           // [B,S,HID]
__device__ __nv_bfloat16 g_a_hi[(size_t)BATCH * S_LEN * HID];  // activation split
__device__ __nv_bfloat16 g_a_lo[(size_t)BATCH * S_LEN * HID];
__device__ __nv_bfloat16 g_wq_hi[(size_t)3 * HID * HID];       // w_qkv^T [3072,1024]
__device__ __nv_bfloat16 g_wq_lo[(size_t)3 * HID * HID];
__device__ __nv_bfloat16 g_wo_hi[(size_t)HID * HID];           // w_out^T [1024,1024]
__device__ __nv_bfloat16 g_wo_lo[(size_t)HID * HID];

// ---------------------------------------------------------------------------
// split: fp32 -> (hi bf16, lo bf16)
// ---------------------------------------------------------------------------
__global__ __launch_bounds__(256) void split_kernel(
    const float* __restrict__ X, __nv_bfloat16* __restrict__ H,
    __nv_bfloat16* __restrict__ L, size_t n4)
{
    size_t i = (size_t)blockIdx.x * blockDim.x + threadIdx.x;
    if (i >= n4) return;
    float4 v = ((const float4*)X)[i];
    __nv_bfloat16 h0 = __float2bfloat16(v.x), h1 = __float2bfloat16(v.y);
    __nv_bfloat16 h2 = __float2bfloat16(v.z), h3 = __float2bfloat16(v.w);
    __nv_bfloat16 l0 = __float2bfloat16(v.x - __bfloat162float(h0));
    __nv_bfloat16 l1 = __float2bfloat16(v.y - __bfloat162float(h1));
    __nv_bfloat16 l2 = __float2bfloat16(v.z - __bfloat162float(h2));
    __nv_bfloat16 l3 = __float2bfloat16(v.w - __bfloat162float(h3));
    __nv_bfloat162 hp0 = {h0, h1}, hp1 = {h2, h3}, lp0 = {l0, l1}, lp1 = {l2, l3};
    uint2 hv = {*(uint32_t*)&hp0, *(uint32_t*)&hp1};
    uint2 lv = {*(uint32_t*)&lp0, *(uint32_t*)&lp1};
    ((uint2*)H)[i] = hv;
    ((uint2*)L)[i] = lv;
}

// ---------------------------------------------------------------------------
// transpose + split: W[K,N] fp32 -> T[N,K] (hi, lo) bf16
// ---------------------------------------------------------------------------
__global__ void transpose_split_kernel(
    const float* __restrict__ W, __nv_bfloat16* __restrict__ Th,
    __nv_bfloat16* __restrict__ Tl, int K, int N)
{
    __shared__ float tile[32][33];
    int n0 = blockIdx.x * 32, k0 = blockIdx.y * 32;
    int tx = threadIdx.x, ty = threadIdx.y;   // 32 x 8
#pragma unroll
    for (int i = 0; i < 32; i += 8)
        tile[ty + i][tx] = W[(size_t)(k0 + ty + i) * N + n0 + tx];
    __syncthreads();
#pragma unroll
    for (int i = 0; i < 32; i += 8) {
        float v = tile[tx][ty + i];
        __nv_bfloat16 h = __float2bfloat16(v);
        __nv_bfloat16 l = __float2bfloat16(v - __bfloat162float(h));
        size_t o = (size_t)(n0 + ty + i) * K + k0 + tx;
        Th[o] = h;
        Tl[o] = l;
    }
}

// ---------------------------------------------------------------------------
// mma.sync bf16 split GEMM: C[M,N] = A[M,K] @ Bt[N,K]^T + bias
// Tile 128x128, BK=32, 8 warps (each 64x32), cp.async 2-stage pipeline.
// smem per tile: 128 rows x LDK bf16 (LDK=40 -> 80B stride, conflict-free).
// ---------------------------------------------------------------------------
#define LDK 40
#define TILE_BYTES (128 * LDK * 2)          // 10240
#define BUF_BYTES  (4 * TILE_BYTES)         // 40960 (Ah, Al, Bh, Bl)
#define GSMEM      (2 * BUF_BYTES)          // 81920

__device__ __forceinline__ uint32_t smem_u32(const void* p) {
    uint32_t a;
    asm("{ .reg .u64 t; cvta.to.shared.u64 t, %1; cvt.u32.u64 %0, t; }" : "=r"(a) : "l"(p));
    return a;
}

__device__ __forceinline__ void cp16(uint32_t dst, const void* src) {
    asm volatile("cp.async.cg.shared.global [%0], [%1], 16;" :: "r"(dst), "l"(src));
}

__device__ __forceinline__ void mma16816(float* d, const uint32_t* a, const uint32_t* b) {
    asm volatile(
        "mma.sync.aligned.m16n8k16.row.col.f32.bf16.bf16.f32 "
        "{%0,%1,%2,%3}, {%4,%5,%6,%7}, {%8,%9}, {%0,%1,%2,%3};"
        : "+f"(d[0]), "+f"(d[1]), "+f"(d[2]), "+f"(d[3])
        : "r"(a[0]), "r"(a[1]), "r"(a[2]), "r"(a[3]), "r"(b[0]), "r"(b[1]));
}

__device__ __forceinline__ void ld_afrag(uint32_t a[4], const __nv_bfloat16* As,
                                         int m, int k, int lane) {
    const __nv_bfloat16* p = As + (size_t)(m + (lane >> 2)) * LDK + k + 2 * (lane & 3);
    a[0] = *(const uint32_t*)p;
    a[1] = *(const uint32_t*)(p + 8 * LDK);
    a[2] = *(const uint32_t*)(p + 8);
    a[3] = *(const uint32_t*)(p + 8 * LDK + 8);
}
__device__ __forceinline__ void ld_bfrag(uint32_t b[2], const __nv_bfloat16* Bs,
                                         int n, int k, int lane) {
    const __nv_bfloat16* p = Bs + (size_t)(n + (lane >> 2)) * LDK + k + 2 * (lane & 3);
    b[0] = *(const uint32_t*)p;
    b[1] = *(const uint32_t*)(p + 8);
}

__global__ __launch_bounds__(256) void gemm_mma_kernel(
    const __nv_bfloat16* __restrict__ Ah, const __nv_bfloat16* __restrict__ Al,
    const __nv_bfloat16* __restrict__ Bh, const __nv_bfloat16* __restrict__ Bl,
    const float* __restrict__ bias, float* __restrict__ C, int M, int N, int K)
{
    extern __shared__ char smem[];
    uint32_t sbase = smem_u32(smem);
    int tid = threadIdx.x, wid = tid >> 5, lane = tid & 31;
    int row0 = blockIdx.y * 128, col0 = blockIdx.x * 128;
    int wm = (wid & 1) * 64;         // warp m offset
    int wn = (wid >> 1) * 32;        // warp n offset

    const __nv_bfloat16* gsrc[4] = {
        Ah + (size_t)row0 * K, Al + (size_t)row0 * K,
        Bh + (size_t)col0 * K, Bl + (size_t)col0 * K };

    float acc[4][4][4];
#pragma unroll
    for (int i = 0; i < 4; i++)
#pragma unroll
        for (int j = 0; j < 4; j++)
#pragma unroll
            for (int e = 0; e < 4; e++) acc[i][j][e] = 0.f;

    const int nit = K / 32;

    // stage loader: 4 tiles x 512 x 16B chunks, 8 chunks/thread
    auto load_stage = [&](int buf, int it) {
        int k0 = it * 32;
        uint32_t sb = sbase + buf * BUF_BYTES;
#pragma unroll
        for (int t = 0; t < 4; t++) {
#pragma unroll
            for (int j = 0; j < 2; j++) {
                int idx = tid + j * 256;          // 0..511
                int r = idx >> 2, seg = idx & 3;
                uint32_t dst = sb + t * TILE_BYTES + (uint32_t)r * (LDK * 2) + seg * 16;
                const void* src = gsrc[t] + (size_t)r * K + k0 + seg * 8;
                cp16(dst, src);
            }
        }
        asm volatile("cp.async.commit_group;" ::: "memory");
    };

    load_stage(0, 0);

    for (int it = 0; it < nit; it++) {
        if (it + 1 < nit) {
            load_stage((it + 1) & 1, it + 1);
            asm volatile("cp.async.wait_group 1;" ::: "memory");
        } else {
            asm volatile("cp.async.wait_group 0;" ::: "memory");
        }
        __syncthreads();

        char* bufp = smem + (it & 1) * BUF_BYTES;
        const __nv_bfloat16* sAh = (const __nv_bfloat16*)(bufp);
        const __nv_bfloat16* sAl = (const __nv_bfloat16*)(bufp + TILE_BYTES);
        const __nv_bfloat16* sBh = (const __nv_bfloat16*)(bufp + 2 * TILE_BYTES);
        const __nv_bfloat16* sBl = (const __nv_bfloat16*)(bufp + 3 * TILE_BYTES);

#pragma unroll
        for (int ks = 0; ks < 32; ks += 16) {
            uint32_t aH[4][4], bH[4][2], tmpA[4][4], tmpB[4][2];
#pragma unroll
            for (int i = 0; i < 4; i++) ld_afrag(aH[i], sAh, wm + i * 16, ks, lane);
#pragma unroll
            for (int j = 0; j < 4; j++) ld_bfrag(bH[j], sBh, wn + j * 8, ks, lane);
#pragma unroll
            for (int i = 0; i < 4; i++)
#pragma unroll
                for (int j = 0; j < 4; j++) mma16816(acc[i][j], aH[i], bH[j]);

#pragma unroll
            for (int j = 0; j < 4; j++) ld_bfrag(tmpB[j], sBl, wn + j * 8, ks, lane);
#pragma unroll
            for (int i = 0; i < 4; i++)
#pragma unroll
                for (int j = 0; j < 4; j++) mma16816(acc[i][j], aH[i], tmpB[j]);

#pragma unroll
            for (int i = 0; i < 4; i++) ld_afrag(tmpA[i], sAl, wm + i * 16, ks, lane);
#pragma unroll
            for (int i = 0; i < 4; i++)
#pragma unroll
                for (int j = 0; j < 4; j++) mma16816(acc[i][j], tmpA[i], bH[j]);
        }
        __syncthreads();
    }

    // epilogue
#pragma unroll
    for (int i = 0; i < 4; i++) {
        int r0 = row0 + wm + i * 16 + (lane >> 2);
#pragma unroll
        for (int j = 0; j < 4; j++) {
            int c = col0 + wn + j * 8 + (lane & 3) * 2;
            float b0 = bias[c], b1 = bias[c + 1];
            float2 v0 = {acc[i][j][0] + b0, acc[i][j][1] + b1};
            float2 v1 = {acc[i][j][2] + b0, acc[i][j][3] + b1};
            *(float2*)(C + (size_t)r0 * N + c) = v0;
            *(float2*)(C + (size_t)(r0 + 8) * N + c) = v1;
        }
    }
}

// ---------------------------------------------------------------------------
// Flash attention (fp32, causal) — unchanged from R1 (passing baseline)
// ---------------------------------------------------------------------------
#define AS 68

__global__ __launch_bounds__(256) void attn_kernel(
    const float* __restrict__ qkv, float* __restrict__ ctx)
{
    extern __shared__ float sm[];
    float* Qs   = sm;
    float* KVs  = sm + 64 * AS;
    float* Ss   = sm + 2 * 64 * AS;
    float* rowC = sm + 3 * 64 * AS;
    float* rowL = rowC + 64;

    int tid = threadIdx.x;
    int qt = blockIdx.x;
    int h  = blockIdx.y;
    int b  = blockIdx.z;
    int q0 = qt * 64;
    const float* base = qkv + (size_t)b * S_LEN * (3 * HID) + h * (3 * HD);

    int lr = tid >> 4;
    int ld = (tid & 15) << 2;

#pragma unroll
    for (int rr = lr; rr < 64; rr += 16)
        *(float4*)&Qs[rr * AS + ld] =
            *(const float4*)&base[(size_t)(q0 + rr) * (3 * HID) + ld];

    int tr = tid >> 4, tc = tid & 15;
    int srow = tid >> 2, sseg = tid & 3;

    float m_i = -INFINITY, l_i = 0.f;
    float acc[4][4];
#pragma unroll
    for (int i = 0; i < 4; i++)
#pragma unroll
        for (int j = 0; j < 4; j++) acc[i][j] = 0.f;

    for (int jt = 0; jt <= qt; jt++) {
        int k0 = jt * 64;
        __syncthreads();

#pragma unroll
        for (int rr = lr; rr < 64; rr += 16)
            *(float4*)&KVs[rr * AS + ld] =
                *(const float4*)&base[(size_t)(k0 + rr) * (3 * HID) + HD + ld];
        __syncthreads();

        float s[4][4];
#pragma unroll
        for (int i = 0; i < 4; i++)
#pragma unroll
            for (int j = 0; j < 4; j++) s[i][j] = 0.f;

#pragma unroll
        for (int kk = 0; kk < 64; kk += 4) {
            float qv[4][4], kv[4][4];
#pragma unroll
            for (int i = 0; i < 4; i++) {
                float4 q4 = *(float4*)&Qs[(tr * 4 + i) * AS + kk];
                qv[i][0] = q4.x; qv[i][1] = q4.y; qv[i][2] = q4.z; qv[i][3] = q4.w;
            }
#pragma unroll
            for (int j = 0; j < 4; j++) {
                float4 k4 = *(float4*)&KVs[(tc + 16 * j) * AS + kk];
                kv[j][0] = k4.x; kv[j][1] = k4.y; kv[j][2] = k4.z; kv[j][3] = k4.w;
            }
#pragma unroll
            for (int i = 0; i < 4; i++)
#pragma unroll
                for (int j = 0; j < 4; j++)
#pragma unroll
                    for (int kc = 0; kc < 4; kc++)
                        s[i][j] += qv[i][kc] * kv[j][kc];
        }
#pragma unroll
        for (int i = 0; i < 4; i++)
#pragma unroll
            for (int j = 0; j < 4; j++) {
                int qg = q0 + tr * 4 + i;
                int kg = k0 + tc + 16 * j;
                float v = s[i][j] * 0.125f;
                if (kg > qg) v = -1e30f;
                Ss[(tr * 4 + i) * AS + tc + 16 * j] = v;
            }
        __syncthreads();

#pragma unroll
        for (int rr = lr; rr < 64; rr += 16)
            *(float4*)&KVs[rr * AS + ld] =
                *(const float4*)&base[(size_t)(k0 + rr) * (3 * HID) + 2 * HD + ld];

        {
            float* sp = &Ss[srow * AS + sseg * 16];
            float tm = -INFINITY;
#pragma unroll
            for (int c = 0; c < 16; c++) tm = fmaxf(tm, sp[c]);
            tm = fmaxf(tm, __shfl_xor_sync(0xffffffffu, tm, 1));
            tm = fmaxf(tm, __shfl_xor_sync(0xffffffffu, tm, 2));
            float m_new = fmaxf(m_i, tm);
            float csum = 0.f;
#pragma unroll
            for (int c = 0; c < 16; c++) {
                float p = __expf(sp[c] - m_new);
                sp[c] = p;
                csum += p;
            }
            csum += __shfl_xor_sync(0xffffffffu, csum, 1);
            csum += __shfl_xor_sync(0xffffffffu, csum, 2);
            float corr = __expf(m_i - m_new);
            l_i = l_i * corr + csum;
            m_i = m_new;
            if (sseg == 0) {
                rowC[srow] = corr;
                if (jt == qt) rowL[srow] = l_i;
            }
        }
        __syncthreads();

        float cf[4];
#pragma unroll
        for (int i = 0; i < 4; i++) cf[i] = rowC[tr * 4 + i];
#pragma unroll
        for (int i = 0; i < 4; i++)
#pragma unroll
            for (int j = 0; j < 4; j++) acc[i][j] *= cf[i];

#pragma unroll
        for (int cc = 0; cc < 64; cc += 4) {
            float pv[4][4], vv[4][4];
#pragma unroll
            for (int i = 0; i < 4; i++) {
                float4 p4 = *(float4*)&Ss[(tr * 4 + i) * AS + cc];
                pv[i][0] = p4.x; pv[i][1] = p4.y; pv[i][2] = p4.z; pv[i][3] = p4.w;
            }
#pragma unroll
            for (int c = 0; c < 4; c++) {
                float4 v4 = *(float4*)&KVs[(cc + c) * AS + tc * 4];
                vv[c][0] = v4.x; vv[c][1] = v4.y; vv[c][2] = v4.z; vv[c][3] = v4.w;
            }
#pragma unroll
            for (int i = 0; i < 4; i++)
#pragma unroll
                for (int j = 0; j < 4; j++)
#pragma unroll
                    for (int c = 0; c < 4; c++)
                        acc[i][j] += pv[i][c] * vv[c][j];
        }
    }

#pragma unroll
    for (int i = 0; i < 4; i++) {
        float inv = 1.0f / rowL[tr * 4 + i];
        float4 o;
        o.x = acc[i][0] * inv;
        o.y = acc[i][1] * inv;
        o.z = acc[i][2] * inv;
        o.w = acc[i][3] * inv;
        *(float4*)&ctx[((size_t)b * S_LEN + q0 + tr * 4 + i) * HID + h * HD + tc * 4] = o;
    }
}

// ---------------------------------------------------------------------------
// kernel_launch
// Inputs: x, mask(ignored: causal), w_qkv, b_qkv, w_out, b_out
// ---------------------------------------------------------------------------
extern "C" void kernel_launch(void* const* d_in, const int* in_sizes, int n_in,
                              void* d_out, int out_size)
{
    const float* x     = (const float*)d_in[0];
    const float* w_qkv = (const float*)d_in[2];
    const float* b_qkv = (const float*)d_in[3];
    const float* w_out = (const float*)d_in[4];
    const float* b_out = (const float*)d_in[5];
    float* out = (float*)d_out;

    float *qkv_ptr, *ctx_ptr;
    __nv_bfloat16 *ah, *al, *wqh, *wql, *woh, *wol;
    cudaGetSymbolAddress((void**)&qkv_ptr, g_qkv);
    cudaGetSymbolAddress((void**)&ctx_ptr, g_ctx);
    cudaGetSymbolAddress((void**)&ah,  g_a_hi);
    cudaGetSymbolAddress((void**)&al,  g_a_lo);
    cudaGetSymbolAddress((void**)&wqh, g_wq_hi);
    cudaGetSymbolAddress((void**)&wql, g_wq_lo);
    cudaGetSymbolAddress((void**)&woh, g_wo_hi);
    cudaGetSymbolAddress((void**)&wol, g_wo_lo);

    const int M = BATCH * S_LEN;   // 8192

    cudaFuncSetAttribute(gemm_mma_kernel,
                         cudaFuncAttributeMaxDynamicSharedMemorySize, GSMEM);
    cudaFuncSetAttribute(attn_kernel,
                         cudaFuncAttributeMaxDynamicSharedMemorySize,
                         (3 * 64 * AS + 128) * (int)sizeof(float));

    // 0) weight transpose+split
    {
        dim3 blk(32, 8);
        transpose_split_kernel<<<dim3((3 * HID) / 32, HID / 32), blk>>>(w_qkv, wqh, wql, HID, 3 * HID);
        transpose_split_kernel<<<dim3(HID / 32, HID / 32), blk>>>(w_out, woh, wol, HID, HID);
    }

    // 1) split x, QKV projection (tensor cores via mma.sync)
    {
        size_t n4 = (size_t)M * HID / 4;
        split_kernel<<<(unsigned)((n4 + 255) / 256), 256>>>(x, ah, al, n4);
        dim3 grid((3 * HID) / 128, M / 128);
        gemm_mma_kernel<<<grid, 256, GSMEM>>>(ah, al, wqh, wql, b_qkv, qkv_ptr,
                                              M, 3 * HID, HID);
    }

    // 2) causal flash attention (fp32)
    {
        int smem = (3 * 64 * AS + 128) * (int)sizeof(float);
        dim3 grid(S_LEN / 64, NH, BATCH);
        attn_kernel<<<grid, 256, smem>>>(qkv_ptr, ctx_ptr);
    }

    // 3) split ctx, output projection
    {
        size_t n4 = (size_t)M * HID / 4;
        split_kernel<<<(unsigned)((n4 + 255) / 256), 256>>>(ctx_ptr, ah, al, n4);
        dim3 grid(HID / 128, M / 128);
        gemm_mma_kernel<<<grid, 256, GSMEM>>>(ah, al, woh, wol, b_out, out,
                                              M, HID, HID);
    }
}

// round 7
// speedup vs baseline: 2.5279x; 1.6300x over previous
#include <cuda_runtime.h>
#include <cuda_bf16.h>
#include <math.h>
#include <stdint.h>

#define BATCH 4
#define S_LEN 2048
#define HID   1024
#define NH    16
#define HD    64

// ---------------------------------------------------------------------------
// Scratch
// ---------------------------------------------------------------------------
__device__ __nv_bfloat16 g_qkv_hi[(size_t)BATCH * S_LEN * 3 * HID];
__device__ __nv_bfloat16 g_qkv_lo[(size_t)BATCH * S_LEN * 3 * HID];
__device__ __nv_bfloat16 g_a_hi[(size_t)BATCH * S_LEN * HID];   // x split, then ctx split
__device__ __nv_bfloat16 g_a_lo[(size_t)BATCH * S_LEN * HID];
__device__ __nv_bfloat16 g_wq_hi[(size_t)3 * HID * HID];
__device__ __nv_bfloat16 g_wq_lo[(size_t)3 * HID * HID];
__device__ __nv_bfloat16 g_wo_hi[(size_t)HID * HID];
__device__ __nv_bfloat16 g_wo_lo[(size_t)HID * HID];

// ---------------------------------------------------------------------------
// common helpers
// ---------------------------------------------------------------------------
__device__ __forceinline__ uint32_t smem_u32(const void* p) {
    uint32_t a;
    asm("{ .reg .u64 t; cvta.to.shared.u64 t, %1; cvt.u32.u64 %0, t; }" : "=r"(a) : "l"(p));
    return a;
}
__device__ __forceinline__ void cp16(uint32_t dst, const void* src) {
    asm volatile("cp.async.cg.shared.global [%0], [%1], 16;" :: "r"(dst), "l"(src));
}
__device__ __forceinline__ void mma16816(float* d, const uint32_t* a, const uint32_t* b) {
    asm volatile(
        "mma.sync.aligned.m16n8k16.row.col.f32.bf16.bf16.f32 "
        "{%0,%1,%2,%3}, {%4,%5,%6,%7}, {%8,%9}, {%0,%1,%2,%3};"
        : "+f"(d[0]), "+f"(d[1]), "+f"(d[2]), "+f"(d[3])
        : "r"(a[0]), "r"(a[1]), "r"(a[2]), "r"(a[3]), "r"(b[0]), "r"(b[1]));
}
__device__ __forceinline__ void ldm_x4(uint32_t* r, uint32_t addr) {
    asm volatile("ldmatrix.sync.aligned.m8n8.x4.shared.b16 {%0,%1,%2,%3}, [%4];"
        : "=r"(r[0]), "=r"(r[1]), "=r"(r[2]), "=r"(r[3]) : "r"(addr));
}
__device__ __forceinline__ void ldm_x4_t(uint32_t* r, uint32_t addr) {
    asm volatile("ldmatrix.sync.aligned.m8n8.x4.trans.shared.b16 {%0,%1,%2,%3}, [%4];"
        : "=r"(r[0]), "=r"(r[1]), "=r"(r[2]), "=r"(r[3]) : "r"(addr));
}
__device__ __forceinline__ uint32_t pack_split(float a, float b, uint32_t& lo) {
    __nv_bfloat162 h, l;
    h.x = __float2bfloat16(a); h.y = __float2bfloat16(b);
    l.x = __float2bfloat16(a - __bfloat162float(h.x));
    l.y = __float2bfloat16(b - __bfloat162float(h.y));
    lo = *(uint32_t*)&l;
    return *(uint32_t*)&h;
}

// ---------------------------------------------------------------------------
// split: fp32 -> (hi, lo) bf16
// ---------------------------------------------------------------------------
__global__ __launch_bounds__(256) void split_kernel(
    const float* __restrict__ X, __nv_bfloat16* __restrict__ H,
    __nv_bfloat16* __restrict__ L, size_t n4)
{
    size_t i = (size_t)blockIdx.x * blockDim.x + threadIdx.x;
    if (i >= n4) return;
    float4 v = ((const float4*)X)[i];
    uint32_t l0, l1;
    uint32_t h0 = pack_split(v.x, v.y, l0);
    uint32_t h1 = pack_split(v.z, v.w, l1);
    uint2 hv = {h0, h1}, lv = {l0, l1};
    ((uint2*)H)[i] = hv;
    ((uint2*)L)[i] = lv;
}

// ---------------------------------------------------------------------------
// transpose + split: W[K,N] fp32 -> T[N,K] (hi, lo) bf16
// ---------------------------------------------------------------------------
__global__ void transpose_split_kernel(
    const float* __restrict__ W, __nv_bfloat16* __restrict__ Th,
    __nv_bfloat16* __restrict__ Tl, int K, int N)
{
    __shared__ float tile[32][33];
    int n0 = blockIdx.x * 32, k0 = blockIdx.y * 32;
    int tx = threadIdx.x, ty = threadIdx.y;
#pragma unroll
    for (int i = 0; i < 32; i += 8)
        tile[ty + i][tx] = W[(size_t)(k0 + ty + i) * N + n0 + tx];
    __syncthreads();
#pragma unroll
    for (int i = 0; i < 32; i += 8) {
        float v = tile[tx][ty + i];
        __nv_bfloat16 h = __float2bfloat16(v);
        __nv_bfloat16 l = __float2bfloat16(v - __bfloat162float(h));
        size_t o = (size_t)(n0 + ty + i) * K + k0 + tx;
        Th[o] = h;
        Tl[o] = l;
    }
}

// ---------------------------------------------------------------------------
// mma.sync split-bf16 GEMM (R3-verified core). mode 0: fp32 out. mode 1:
// split hi/lo bf16 out (for qkv).
// ---------------------------------------------------------------------------
#define LDK 40
#define TILE_BYTES (128 * LDK * 2)
#define BUF_BYTES  (4 * TILE_BYTES)
#define GSMEM      (2 * BUF_BYTES)

__device__ __forceinline__ void ld_afrag(uint32_t a[4], const __nv_bfloat16* As,
                                         int m, int k, int lane) {
    const __nv_bfloat16* p = As + (size_t)(m + (lane >> 2)) * LDK + k + 2 * (lane & 3);
    a[0] = *(const uint32_t*)p;
    a[1] = *(const uint32_t*)(p + 8 * LDK);
    a[2] = *(const uint32_t*)(p + 8);
    a[3] = *(const uint32_t*)(p + 8 * LDK + 8);
}
__device__ __forceinline__ void ld_bfrag(uint32_t b[2], const __nv_bfloat16* Bs,
                                         int n, int k, int lane) {
    const __nv_bfloat16* p = Bs + (size_t)(n + (lane >> 2)) * LDK + k + 2 * (lane & 3);
    b[0] = *(const uint32_t*)p;
    b[1] = *(const uint32_t*)(p + 8);
}

__global__ __launch_bounds__(256) void gemm_mma_kernel(
    const __nv_bfloat16* __restrict__ Ah, const __nv_bfloat16* __restrict__ Al,
    const __nv_bfloat16* __restrict__ Bh, const __nv_bfloat16* __restrict__ Bl,
    const float* __restrict__ bias, float* __restrict__ Cf,
    __nv_bfloat16* __restrict__ Ch, __nv_bfloat16* __restrict__ Cl,
    int M, int N, int K, int mode)
{
    extern __shared__ char smem[];
    uint32_t sbase = smem_u32(smem);
    int tid = threadIdx.x, wid = tid >> 5, lane = tid & 31;
    int row0 = blockIdx.y * 128, col0 = blockIdx.x * 128;
    int wm = (wid & 1) * 64;
    int wn = (wid >> 1) * 32;

    const __nv_bfloat16* gsrc[4] = {
        Ah + (size_t)row0 * K, Al + (size_t)row0 * K,
        Bh + (size_t)col0 * K, Bl + (size_t)col0 * K };

    float acc[4][4][4];
#pragma unroll
    for (int i = 0; i < 4; i++)
#pragma unroll
        for (int j = 0; j < 4; j++)
#pragma unroll
            for (int e = 0; e < 4; e++) acc[i][j][e] = 0.f;

    const int nit = K / 32;

    auto load_stage = [&](int buf, int it) {
        int k0 = it * 32;
        uint32_t sb = sbase + buf * BUF_BYTES;
#pragma unroll
        for (int t = 0; t < 4; t++) {
#pragma unroll
            for (int j = 0; j < 2; j++) {
                int idx = tid + j * 256;
                int r = idx >> 2, seg = idx & 3;
                uint32_t dst = sb + t * TILE_BYTES + (uint32_t)r * (LDK * 2) + seg * 16;
                const void* src = gsrc[t] + (size_t)r * K + k0 + seg * 8;
                cp16(dst, src);
            }
        }
        asm volatile("cp.async.commit_group;" ::: "memory");
    };

    load_stage(0, 0);

    for (int it = 0; it < nit; it++) {
        if (it + 1 < nit) {
            load_stage((it + 1) & 1, it + 1);
            asm volatile("cp.async.wait_group 1;" ::: "memory");
        } else {
            asm volatile("cp.async.wait_group 0;" ::: "memory");
        }
        __syncthreads();

        char* bufp = smem + (it & 1) * BUF_BYTES;
        const __nv_bfloat16* sAh = (const __nv_bfloat16*)(bufp);
        const __nv_bfloat16* sAl = (const __nv_bfloat16*)(bufp + TILE_BYTES);
        const __nv_bfloat16* sBh = (const __nv_bfloat16*)(bufp + 2 * TILE_BYTES);
        const __nv_bfloat16* sBl = (const __nv_bfloat16*)(bufp + 3 * TILE_BYTES);

#pragma unroll
        for (int ks = 0; ks < 32; ks += 16) {
            uint32_t aH[4][4], bH[4][2], tmpA[4][4], tmpB[4][2];
#pragma unroll
            for (int i = 0; i < 4; i++) ld_afrag(aH[i], sAh, wm + i * 16, ks, lane);
#pragma unroll
            for (int j = 0; j < 4; j++) ld_bfrag(bH[j], sBh, wn + j * 8, ks, lane);
#pragma unroll
            for (int i = 0; i < 4; i++)
#pragma unroll
                for (int j = 0; j < 4; j++) mma16816(acc[i][j], aH[i], bH[j]);

#pragma unroll
            for (int j = 0; j < 4; j++) ld_bfrag(tmpB[j], sBl, wn + j * 8, ks, lane);
#pragma unroll
            for (int i = 0; i < 4; i++)
#pragma unroll
                for (int j = 0; j < 4; j++) mma16816(acc[i][j], aH[i], tmpB[j]);

#pragma unroll
            for (int i = 0; i < 4; i++) ld_afrag(tmpA[i], sAl, wm + i * 16, ks, lane);
#pragma unroll
            for (int i = 0; i < 4; i++)
#pragma unroll
                for (int j = 0; j < 4; j++) mma16816(acc[i][j], tmpA[i], bH[j]);
        }
        __syncthreads();
    }

#pragma unroll
    for (int i = 0; i < 4; i++) {
        int r0 = row0 + wm + i * 16 + (lane >> 2);
#pragma unroll
        for (int j = 0; j < 4; j++) {
            int c = col0 + wn + j * 8 + (lane & 3) * 2;
            float b0 = bias[c], b1 = bias[c + 1];
            float v00 = acc[i][j][0] + b0, v01 = acc[i][j][1] + b1;
            float v10 = acc[i][j][2] + b0, v11 = acc[i][j][3] + b1;
            if (mode == 0) {
                float2 p0 = {v00, v01}, p1 = {v10, v11};
                *(float2*)(Cf + (size_t)r0 * N + c) = p0;
                *(float2*)(Cf + (size_t)(r0 + 8) * N + c) = p1;
            } else {
                uint32_t l0, l1;
                uint32_t h0 = pack_split(v00, v01, l0);
                uint32_t h1 = pack_split(v10, v11, l1);
                *(uint32_t*)(Ch + (size_t)r0 * N + c) = h0;
                *(uint32_t*)(Cl + (size_t)r0 * N + c) = l0;
                *(uint32_t*)(Ch + (size_t)(r0 + 8) * N + c) = h1;
                *(uint32_t*)(Cl + (size_t)(r0 + 8) * N + c) = l1;
            }
        }
    }
}

// ---------------------------------------------------------------------------
// Flash attention on mma.sync, split-bf16, causal.
// CTA: 128 q-rows x one (b,h). 8 warps, each 16 q-rows x all 128 kv cols.
// KV tiles of 128, double-buffered via cp.async.
// ---------------------------------------------------------------------------
#define LDA 72                         // row stride in bf16 elems (144B)
#define ATILE (128 * LDA * 2)          // 18432 B per 128x64 bf16 tile
#define AKV   (4 * ATILE)              // Kh,Kl,Vh,Vl per buffer
#define ASMEM (2 * ATILE + 2 * AKV)    // Qh,Ql + 2 KV buffers = 184320 B

__global__ __launch_bounds__(256) void attn_mma_kernel(
    const __nv_bfloat16* __restrict__ qkv_hi,
    const __nv_bfloat16* __restrict__ qkv_lo,
    __nv_bfloat16* __restrict__ ctx_hi,
    __nv_bfloat16* __restrict__ ctx_lo)
{
    extern __shared__ char smem[];
    uint32_t sbase = smem_u32(smem);
    int tid = threadIdx.x, wid = tid >> 5, lane = tid & 31;
    int qt = blockIdx.x, h = blockIdx.y, b = blockIdx.z;
    int q0 = qt * 128;

    const size_t rstride = 3 * HID;                       // 3072 elems
    const size_t hoff = (size_t)b * S_LEN * rstride + (size_t)h * (3 * HD);
    const __nv_bfloat16* bh = qkv_hi + hoff;
    const __nv_bfloat16* bl = qkv_lo + hoff;

    // ---- load Q tiles (hi/lo) ----
    {
#pragma unroll
        for (int j = 0; j < 4; j++) {
            int idx = tid + j * 256;                      // 0..1023
            int r = idx >> 3, c = idx & 7;
            size_t go = (size_t)(q0 + r) * rstride + c * 8;
            uint32_t dst = (uint32_t)(r * (LDA * 2) + c * 16);
            cp16(sbase + dst, bh + go);
            cp16(sbase + ATILE + dst, bl + go);
        }
        asm volatile("cp.async.commit_group;" ::: "memory");
    }

    auto load_kv = [&](int buf, int jt) {
        uint32_t kb = sbase + 2 * ATILE + buf * AKV;
#pragma unroll
        for (int j = 0; j < 4; j++) {
            int idx = tid + j * 256;
            int r = idx >> 3, c = idx & 7;
            size_t go = (size_t)(jt * 128 + r) * rstride + c * 8;
            uint32_t dst = (uint32_t)(r * (LDA * 2) + c * 16);
            cp16(kb + dst,              bh + go + HD);        // K hi
            cp16(kb + ATILE + dst,      bl + go + HD);        // K lo
            cp16(kb + 2 * ATILE + dst,  bh + go + 2 * HD);    // V hi
            cp16(kb + 3 * ATILE + dst,  bl + go + 2 * HD);    // V lo
        }
        asm volatile("cp.async.commit_group;" ::: "memory");
    };

    load_kv(0, 0);

    // per-thread fragment address components
    int aArow = wid * 16 + (lane & 7) + ((lane >> 3) & 1) * 8;  // Q row
    int aAcol = (lane >> 4) * 8;                                // + kd
    int bKrow = (lane & 7) + (lane >> 4) * 8;                   // + n16
    int bKcol = ((lane >> 3) & 1) * 8;                          // + kd
    int vRow  = (lane & 7) + ((lane >> 3) & 1) * 8;             // + kv16
    int vCol  = (lane >> 4) * 8;                                // + d16

    int rowg0 = q0 + wid * 16 + (lane >> 2);                    // global q row
    int colB  = 2 * (lane & 3);                                 // col base in n8 tile

    float m0 = -INFINITY, m1 = -INFINITY, l0 = 0.f, l1 = 0.f;
    float o[8][4];
#pragma unroll
    for (int t = 0; t < 8; t++)
#pragma unroll
        for (int e = 0; e < 4; e++) o[t][e] = 0.f;

    for (int jt = 0; jt <= qt; jt++) {
        int buf = jt & 1;
        if (jt < qt) {
            load_kv(buf ^ 1, jt + 1);
            asm volatile("cp.async.wait_group 1;" ::: "memory");
        } else {
            asm volatile("cp.async.wait_group 0;" ::: "memory");
        }
        __syncthreads();

        uint32_t kb = sbase + 2 * ATILE + buf * AKV;
        uint32_t Qh_a = sbase + aArow * (LDA * 2) + aAcol * 2;
        uint32_t Ql_a = Qh_a + ATILE;

        // ---- GEMM1: S = Q @ K^T (split) ----
        float s[16][4];
#pragma unroll
        for (int i = 0; i < 16; i++)
#pragma unroll
            for (int e = 0; e < 4; e++) s[i][e] = 0.f;

#pragma unroll
        for (int kd = 0; kd < 64; kd += 16) {
            uint32_t aH[4], aL[4];
            ldm_x4(aH, Qh_a + kd * 2);
            ldm_x4(aL, Ql_a + kd * 2);
#pragma unroll
            for (int t = 0; t < 8; t++) {
                uint32_t bHf[4], bLf[4];
                uint32_t ka = kb + (uint32_t)((16 * t + bKrow) * (LDA * 2) + (kd + bKcol) * 2);
                ldm_x4(bHf, ka);
                ldm_x4(bLf, ka + ATILE);
                mma16816(s[2 * t],     aH, bHf);
                mma16816(s[2 * t],     aH, bLf);
                mma16816(s[2 * t],     aL, bHf);
                mma16816(s[2 * t + 1], aH, bHf + 2);
                mma16816(s[2 * t + 1], aH, bLf + 2);
                mma16816(s[2 * t + 1], aL, bHf + 2);
            }
        }

        // ---- scale + causal mask ----
        int k0 = jt * 128;
#pragma unroll
        for (int i = 0; i < 16; i++)
#pragma unroll
            for (int e = 0; e < 4; e++) s[i][e] *= 0.125f;
        if (jt == qt) {
#pragma unroll
            for (int i = 0; i < 16; i++) {
                int cg = k0 + 8 * i + colB;
                if (cg > rowg0)     s[i][0] = -1e30f;
                if (cg + 1 > rowg0) s[i][1] = -1e30f;
                if (cg > rowg0 + 8)     s[i][2] = -1e30f;
                if (cg + 1 > rowg0 + 8) s[i][3] = -1e30f;
            }
        }

        // ---- online softmax ----
        float mx0 = -INFINITY, mx1 = -INFINITY;
#pragma unroll
        for (int i = 0; i < 16; i++) {
            mx0 = fmaxf(mx0, fmaxf(s[i][0], s[i][1]));
            mx1 = fmaxf(mx1, fmaxf(s[i][2], s[i][3]));
        }
        mx0 = fmaxf(mx0, __shfl_xor_sync(0xffffffffu, mx0, 1));
        mx0 = fmaxf(mx0, __shfl_xor_sync(0xffffffffu, mx0, 2));
        mx1 = fmaxf(mx1, __shfl_xor_sync(0xffffffffu, mx1, 1));
        mx1 = fmaxf(mx1, __shfl_xor_sync(0xffffffffu, mx1, 2));
        float mn0 = fmaxf(m0, mx0), mn1 = fmaxf(m1, mx1);
        float sum0 = 0.f, sum1 = 0.f;
#pragma unroll
        for (int i = 0; i < 16; i++) {
            s[i][0] = __expf(s[i][0] - mn0);
            s[i][1] = __expf(s[i][1] - mn0);
            s[i][2] = __expf(s[i][2] - mn1);
            s[i][3] = __expf(s[i][3] - mn1);
            sum0 += s[i][0] + s[i][1];
            sum1 += s[i][2] + s[i][3];
        }
        sum0 += __shfl_xor_sync(0xffffffffu, sum0, 1);
        sum0 += __shfl_xor_sync(0xffffffffu, sum0, 2);
        sum1 += __shfl_xor_sync(0xffffffffu, sum1, 1);
        sum1 += __shfl_xor_sync(0xffffffffu, sum1, 2);
        float c0 = __expf(m0 - mn0), c1 = __expf(m1 - mn1);
        l0 = l0 * c0 + sum0;
        l1 = l1 * c1 + sum1;
        m0 = mn0; m1 = mn1;
#pragma unroll
        for (int t = 0; t < 8; t++) {
            o[t][0] *= c0; o[t][1] *= c0;
            o[t][2] *= c1; o[t][3] *= c1;
        }

        // ---- GEMM2: acc += P @ V (split; P from registers) ----
#pragma unroll
        for (int kt = 0; kt < 8; kt++) {
            uint32_t pH[4], pL[4];
            pH[0] = pack_split(s[2 * kt][0],     s[2 * kt][1],     pL[0]);
            pH[1] = pack_split(s[2 * kt][2],     s[2 * kt][3],     pL[1]);
            pH[2] = pack_split(s[2 * kt + 1][0], s[2 * kt + 1][1], pL[2]);
            pH[3] = pack_split(s[2 * kt + 1][2], s[2 * kt + 1][3], pL[3]);
#pragma unroll
            for (int t = 0; t < 4; t++) {
                uint32_t bHf[4], bLf[4];
                uint32_t va = kb + 2 * ATILE +
                    (uint32_t)((16 * kt + vRow) * (LDA * 2) + (16 * t + vCol) * 2);
                ldm_x4_t(bHf, va);
                ldm_x4_t(bLf, va + ATILE);
                mma16816(o[2 * t],     pH, bHf);
                mma16816(o[2 * t],     pH, bLf);
                mma16816(o[2 * t],     pL, bHf);
                mma16816(o[2 * t + 1], pH, bHf + 2);
                mma16816(o[2 * t + 1], pH, bLf + 2);
                mma16816(o[2 * t + 1], pL, bHf + 2);
            }
        }
        __syncthreads();
    }

    // ---- epilogue: normalize, split, store ctx hi/lo ----
    float inv0 = 1.0f / l0, inv1 = 1.0f / l1;
    size_t r0 = (size_t)b * S_LEN + rowg0;
#pragma unroll
    for (int t = 0; t < 8; t++) {
        size_t c = (size_t)h * HD + 8 * t + colB;
        uint32_t lo0, lo1;
        uint32_t hi0 = pack_split(o[t][0] * inv0, o[t][1] * inv0, lo0);
        uint32_t hi1 = pack_split(o[t][2] * inv1, o[t][3] * inv1, lo1);
        *(uint32_t*)(ctx_hi + r0 * HID + c) = hi0;
        *(uint32_t*)(ctx_lo + r0 * HID + c) = lo0;
        *(uint32_t*)(ctx_hi + (r0 + 8) * HID + c) = hi1;
        *(uint32_t*)(ctx_lo + (r0 + 8) * HID + c) = lo1;
    }
}

// ---------------------------------------------------------------------------
// kernel_launch
// ---------------------------------------------------------------------------
extern "C" void kernel_launch(void* const* d_in, const int* in_sizes, int n_in,
                              void* d_out, int out_size)
{
    const float* x     = (const float*)d_in[0];
    const float* w_qkv = (const float*)d_in[2];
    const float* b_qkv = (const float*)d_in[3];
    const float* w_out = (const float*)d_in[4];
    const float* b_out = (const float*)d_in[5];
    float* out = (float*)d_out;

    __nv_bfloat16 *qh, *ql, *ah, *al, *wqh, *wql, *woh, *wol;
    cudaGetSymbolAddress((void**)&qh,  g_qkv_hi);
    cudaGetSymbolAddress((void**)&ql,  g_qkv_lo);
    cudaGetSymbolAddress((void**)&ah,  g_a_hi);
    cudaGetSymbolAddress((void**)&al,  g_a_lo);
    cudaGetSymbolAddress((void**)&wqh, g_wq_hi);
    cudaGetSymbolAddress((void**)&wql, g_wq_lo);
    cudaGetSymbolAddress((void**)&woh, g_wo_hi);
    cudaGetSymbolAddress((void**)&wol, g_wo_lo);

    const int M = BATCH * S_LEN;

    cudaFuncSetAttribute(gemm_mma_kernel,
                         cudaFuncAttributeMaxDynamicSharedMemorySize, GSMEM);
    cudaFuncSetAttribute(attn_mma_kernel,
                         cudaFuncAttributeMaxDynamicSharedMemorySize, ASMEM);

    // 0) weight transpose+split
    {
        dim3 blk(32, 8);
        transpose_split_kernel<<<dim3((3 * HID) / 32, HID / 32), blk>>>(w_qkv, wqh, wql, HID, 3 * HID);
        transpose_split_kernel<<<dim3(HID / 32, HID / 32), blk>>>(w_out, woh, wol, HID, HID);
    }

    // 1) split x; QKV projection -> split bf16 qkv
    {
        size_t n4 = (size_t)M * HID / 4;
        split_kernel<<<(unsigned)((n4 + 255) / 256), 256>>>(x, ah, al, n4);
        dim3 grid((3 * HID) / 128, M / 128);
        gemm_mma_kernel<<<grid, 256, GSMEM>>>(ah, al, wqh, wql, b_qkv,
                                              nullptr, qh, ql, M, 3 * HID, HID, 1);
    }

    // 2) causal flash attention (mma.sync) -> ctx hi/lo
    {
        dim3 grid(S_LEN / 128, NH, BATCH);
        attn_mma_kernel<<<grid, 256, ASMEM>>>(qh, ql, ah, al);
    }

    // 3) output projection -> fp32 out
    {
        dim3 grid(HID / 128, M / 128);
        gemm_mma_kernel<<<grid, 256, GSMEM>>>(ah, al, woh, wol, b_out,
                                              out, nullptr, nullptr, M, HID, HID, 0);
    }
}